// round 8
// baseline (speedup 1.0000x reference)
#include <cuda_runtime.h>
#include <cuda_bf16.h>
#include <cstdint>
#include <cstddef>

// ---------------------------------------------------------------------------
// GatedGraphConv (10 layers) + GRUCell.
// Fusion: segment_sum linear => gi = scatter_add(h) @ (w_ih @ W_l^T)^T + b_ih
// GEMMs: mma.sync m16n8k16 bf16 (baseline PTX -- sm_103 target has no
// tcgen05), fp32 accuracy via bf16 hi/lo split: AB ~= AhBh + AhBl + AlBh.
// ---------------------------------------------------------------------------

#define C_DIM 128
#define N_MAX 100352
#define E_MAX 1048576
#define L_MAX 16

__device__ __align__(128) float g_h  [(size_t)N_MAX * C_DIM];
__device__ __align__(128) float g_agg[(size_t)N_MAX * C_DIM];
__device__ __align__(128) float g_gi [(size_t)N_MAX * 3 * C_DIM];
__device__ __align__(128) float g_gh [(size_t)N_MAX * 3 * C_DIM];
__device__ __align__(128) float g_bl [(size_t)L_MAX * 3 * C_DIM * C_DIM];
__device__ __align__(128) __nv_bfloat16 g_bl_hi [(size_t)L_MAX * 3 * C_DIM * C_DIM];
__device__ __align__(128) __nv_bfloat16 g_bl_lo [(size_t)L_MAX * 3 * C_DIM * C_DIM];
__device__ __align__(128) __nv_bfloat16 g_whh_hi[(size_t)3 * C_DIM * C_DIM];
__device__ __align__(128) __nv_bfloat16 g_whh_lo[(size_t)3 * C_DIM * C_DIM];
__device__ __align__(128) int   g_src[E_MAX];
__device__ __align__(128) int   g_dst[E_MAX];
__device__ int g_is64;

// ============================ helpers ======================================
__device__ __forceinline__ uint32_t smem_u32(const void* p) {
    uint32_t a;
    asm("{ .reg .u64 t; cvta.to.shared.u64 t, %1; cvt.u32.u64 %0, t; }" : "=r"(a) : "l"(p));
    return a;
}
__device__ __forceinline__ void ldmatrix_x4(uint32_t& r0, uint32_t& r1,
                                            uint32_t& r2, uint32_t& r3, uint32_t addr) {
    asm volatile("ldmatrix.sync.aligned.m8n8.x4.shared.b16 {%0,%1,%2,%3}, [%4];"
                 : "=r"(r0), "=r"(r1), "=r"(r2), "=r"(r3) : "r"(addr));
}
__device__ __forceinline__ void mma_bf16(float* d, const uint32_t* a, const uint32_t* b) {
    asm volatile(
        "mma.sync.aligned.m16n8k16.row.col.f32.bf16.bf16.f32 "
        "{%0,%1,%2,%3}, {%4,%5,%6,%7}, {%8,%9}, {%0,%1,%2,%3};"
        : "+f"(d[0]), "+f"(d[1]), "+f"(d[2]), "+f"(d[3])
        : "r"(a[0]), "r"(a[1]), "r"(a[2]), "r"(a[3]), "r"(b[0]), "r"(b[1]));
}

// ============================ small kernels ================================
__global__ void detect_edge_dtype_kernel(const int* __restrict__ e32, int nscan) {
    if (threadIdx.x == 0 && blockIdx.x == 0) {
        int acc = 0;
        for (int i = 1; i < nscan; i += 2) acc |= e32[i];
        g_is64 = (acc == 0) ? 1 : 0;
    }
}
__global__ void decode_edges_kernel(const int* __restrict__ e32, int E) {
    int i = blockIdx.x * blockDim.x + threadIdx.x;
    if (i >= E) return;
    if (g_is64) { g_src[i] = e32[2 * (size_t)i]; g_dst[i] = e32[2 * ((size_t)E + i)]; }
    else        { g_src[i] = e32[i];             g_dst[i] = e32[(size_t)E + i]; }
}
__global__ void copy_f4_kernel(const float4* __restrict__ s, float4* __restrict__ d, int n4) {
    int i = blockIdx.x * blockDim.x + threadIdx.x;
    if (i < n4) d[i] = s[i];
}
__global__ void zero_f4_kernel(float4* __restrict__ p, int n4) {
    int i = blockIdx.x * blockDim.x + threadIdx.x;
    if (i < n4) p[i] = make_float4(0.f, 0.f, 0.f, 0.f);
}
__global__ void split_bf16_kernel(const float* __restrict__ src,
                                  __nv_bfloat16* __restrict__ hi,
                                  __nv_bfloat16* __restrict__ lo, int n) {
    int i = blockIdx.x * blockDim.x + threadIdx.x;
    if (i >= n) return;
    float v = src[i];
    __nv_bfloat16 h = __float2bfloat16(v);
    hi[i] = h;
    lo[i] = __float2bfloat16(v - __bfloat162float(h));
}

// ================= SIMT NT GEMM (tiny B_l precompute, batched over z) ======
__global__ void __launch_bounds__(256) gemm_nt_batched_kernel(
    const float* __restrict__ A, const float* __restrict__ Wall,
    float* __restrict__ CoutAll, int M, int nout)
{
    __shared__ float As[64][68];
    __shared__ float Bs[64][68];
    const float* B = Wall + (size_t)blockIdx.z * C_DIM * C_DIM;
    float* Cout = CoutAll + (size_t)blockIdx.z * 3 * C_DIM * C_DIM;
    const int tid = threadIdx.x;
    const int row0 = blockIdx.x * 64, col0 = blockIdx.y * 64;
    const int tx = tid & 15, ty = tid >> 4;
    float acc[4][4];
#pragma unroll
    for (int i = 0; i < 4; i++)
#pragma unroll
        for (int j = 0; j < 4; j++) acc[i][j] = 0.f;
#pragma unroll
    for (int kt = 0; kt < 2; kt++) {
#pragma unroll
        for (int s = 0; s < 4; s++) {
            int i = tid + s * 256, r = i >> 4, c4 = i & 15;
            float4 va = make_float4(0.f, 0.f, 0.f, 0.f);
            if (row0 + r < M)
                va = *reinterpret_cast<const float4*>(A + (size_t)(row0 + r) * C_DIM + kt * 64 + c4 * 4);
            *reinterpret_cast<float4*>(&As[r][c4 * 4]) = va;
            float4 vb = *reinterpret_cast<const float4*>(B + (size_t)(col0 + r) * C_DIM + kt * 64 + c4 * 4);
            *reinterpret_cast<float4*>(&Bs[r][c4 * 4]) = vb;
        }
        __syncthreads();
#pragma unroll
        for (int k4 = 0; k4 < 16; k4++) {
            float4 a[4], b[4];
#pragma unroll
            for (int i = 0; i < 4; i++) a[i] = *reinterpret_cast<const float4*>(&As[ty * 4 + i][k4 * 4]);
#pragma unroll
            for (int j = 0; j < 4; j++) b[j] = *reinterpret_cast<const float4*>(&Bs[tx * 4 + j][k4 * 4]);
#pragma unroll
            for (int i = 0; i < 4; i++)
#pragma unroll
                for (int j = 0; j < 4; j++) {
                    acc[i][j] += a[i].x * b[j].x; acc[i][j] += a[i].y * b[j].y;
                    acc[i][j] += a[i].z * b[j].z; acc[i][j] += a[i].w * b[j].w;
                }
        }
        __syncthreads();
    }
#pragma unroll
    for (int i = 0; i < 4; i++) {
        int r = row0 + ty * 4 + i;
        if (r < M)
#pragma unroll
            for (int j = 0; j < 4; j++)
                Cout[(size_t)r * nout + col0 + tx * 4 + j] = acc[i][j];
    }
}

// ======================= HMMA GEMM (the hot path) ==========================
// C[M x 384] = A[M x 128](fp32) * B[384 x 128]^T(bf16 hi/lo) + bias
// CTA tile 128x128, K=128 fully resident in smem. 512 threads, warp grid
// 4x4, warp tile 32x32 (2 m-frags x 4 n-frags), 3 mma per frag (split).
// Padded smem rows: 136 bf16 = 272 B = 17 x 16B  -> ldmatrix conflict-free.
#define LDA_B 272                 // bytes per padded row
#define TILE_B (128 * LDA_B)      // 34816 bytes per tile
#define SM_TOT (4 * TILE_B)       // A_hi, A_lo, B_hi, B_lo

__global__ void __launch_bounds__(512, 1)
mma_gemm_kernel(const float* __restrict__ A,
                const __nv_bfloat16* __restrict__ Bhi,
                const __nv_bfloat16* __restrict__ Blo,
                const float* __restrict__ bias,
                float* __restrict__ Cout, int M)
{
    extern __shared__ char smem[];
    char* sAhi = smem;
    char* sAlo = smem + TILE_B;
    char* sBhi = smem + 2 * TILE_B;
    char* sBlo = smem + 3 * TILE_B;

    const int tid  = threadIdx.x;
    const int wid  = tid >> 5;
    const int lane = tid & 31;
    const int row0 = blockIdx.x * 128;
    const int col0 = blockIdx.y * 128;

    // ---- load A (fp32), split to bf16 hi/lo, store to padded smem ----
#pragma unroll
    for (int it = 0; it < 8; it++) {
        int idx = tid + it * 512;          // 0..4095 float4 index
        int row = idx >> 5;                // 0..127
        int kk  = (idx & 31) * 4;          // 0..124
        float4 v = make_float4(0.f, 0.f, 0.f, 0.f);
        if (row0 + row < M)
            v = *reinterpret_cast<const float4*>(A + (size_t)(row0 + row) * C_DIM + kk);
        __nv_bfloat16 hx = __float2bfloat16(v.x), hy = __float2bfloat16(v.y);
        __nv_bfloat16 hz = __float2bfloat16(v.z), hw = __float2bfloat16(v.w);
        __nv_bfloat16 ox = __float2bfloat16(v.x - __bfloat162float(hx));
        __nv_bfloat16 oy = __float2bfloat16(v.y - __bfloat162float(hy));
        __nv_bfloat16 oz = __float2bfloat16(v.z - __bfloat162float(hz));
        __nv_bfloat16 ow = __float2bfloat16(v.w - __bfloat162float(hw));
        uint32_t h01 = (uint32_t)__bfloat16_as_ushort(hx) | ((uint32_t)__bfloat16_as_ushort(hy) << 16);
        uint32_t h23 = (uint32_t)__bfloat16_as_ushort(hz) | ((uint32_t)__bfloat16_as_ushort(hw) << 16);
        uint32_t l01 = (uint32_t)__bfloat16_as_ushort(ox) | ((uint32_t)__bfloat16_as_ushort(oy) << 16);
        uint32_t l23 = (uint32_t)__bfloat16_as_ushort(oz) | ((uint32_t)__bfloat16_as_ushort(ow) << 16);
        uint32_t off = (uint32_t)row * LDA_B + kk * 2;
        *reinterpret_cast<uint2*>(sAhi + off) = make_uint2(h01, h23);
        *reinterpret_cast<uint2*>(sAlo + off) = make_uint2(l01, l23);
    }

    // ---- load B (pre-split bf16) to padded smem ----
#pragma unroll
    for (int it = 0; it < 4; it++) {
        int idx = tid + it * 512;          // 0..2047 uint4 index
        int r   = idx >> 4;                // 0..127
        int k0  = (idx & 15) * 8;          // 0..120
        uint4 vh = *reinterpret_cast<const uint4*>(Bhi + (size_t)(col0 + r) * C_DIM + k0);
        uint4 vl = *reinterpret_cast<const uint4*>(Blo + (size_t)(col0 + r) * C_DIM + k0);
        uint32_t off = (uint32_t)r * LDA_B + k0 * 2;
        *reinterpret_cast<uint4*>(sBhi + off) = vh;
        *reinterpret_cast<uint4*>(sBlo + off) = vl;
    }
    __syncthreads();

    // ---- compute: warp (wm, wn) covers rows wm*32..+31, cols wn*32..+31 ----
    const int wm = wid & 3;
    const int wn = wid >> 2;

    // ldmatrix lane addressing
    // A: row = tile_row + lane%16, col byte = (lane/16)*16
    const uint32_t a_base_off =
        (uint32_t)(wm * 32 + (lane & 15)) * LDA_B + (uint32_t)(lane >> 4) * 16;
    uint32_t aHaddr = smem_u32(sAhi) + a_base_off;
    uint32_t aLaddr = smem_u32(sAlo) + a_base_off;
    // B: g = lane/8; row = tile_col + (g>>1)*8 + lane%8 ; col byte = (g&1)*16
    const uint32_t b_base_off =
        (uint32_t)(wn * 32 + ((lane >> 4) & 1) * 8 + (lane & 7)) * LDA_B +
        (uint32_t)((lane >> 3) & 1) * 16;
    uint32_t bHaddr = smem_u32(sBhi) + b_base_off;
    uint32_t bLaddr = smem_u32(sBlo) + b_base_off;

    float acc[2][4][4];
#pragma unroll
    for (int im = 0; im < 2; im++)
#pragma unroll
        for (int in = 0; in < 4; in++)
#pragma unroll
            for (int q = 0; q < 4; q++) acc[im][in][q] = 0.f;

#pragma unroll
    for (int ks = 0; ks < 8; ks++) {
        const uint32_t koff = ks * 32;   // 16 bf16 = 32 bytes per kstep
        uint32_t aH[2][4], aL[2][4], bH[4][2], bL[4][2];
#pragma unroll
        for (int im = 0; im < 2; im++) {
            ldmatrix_x4(aH[im][0], aH[im][1], aH[im][2], aH[im][3],
                        aHaddr + (uint32_t)im * 16 * LDA_B + koff);
            ldmatrix_x4(aL[im][0], aL[im][1], aL[im][2], aL[im][3],
                        aLaddr + (uint32_t)im * 16 * LDA_B + koff);
        }
#pragma unroll
        for (int io = 0; io < 2; io++) {
            uint32_t r0, r1, r2, r3;
            ldmatrix_x4(r0, r1, r2, r3, bHaddr + (uint32_t)io * 16 * LDA_B + koff);
            bH[io * 2 + 0][0] = r0; bH[io * 2 + 0][1] = r1;
            bH[io * 2 + 1][0] = r2; bH[io * 2 + 1][1] = r3;
            ldmatrix_x4(r0, r1, r2, r3, bLaddr + (uint32_t)io * 16 * LDA_B + koff);
            bL[io * 2 + 0][0] = r0; bL[io * 2 + 0][1] = r1;
            bL[io * 2 + 1][0] = r2; bL[io * 2 + 1][1] = r3;
        }
#pragma unroll
        for (int im = 0; im < 2; im++)
#pragma unroll
            for (int in = 0; in < 4; in++) {
                mma_bf16(acc[im][in], aH[im], bH[in]);
                mma_bf16(acc[im][in], aH[im], bL[in]);
                mma_bf16(acc[im][in], aL[im], bH[in]);
            }
    }

    // ---- epilogue ----
    const int row_l = lane >> 2;          // 0..7
    const int col_l = (lane & 3) * 2;     // 0,2,4,6
#pragma unroll
    for (int im = 0; im < 2; im++) {
#pragma unroll
        for (int in = 0; in < 4; in++) {
            int col = col0 + wn * 32 + in * 8 + col_l;
            float bx = __ldg(bias + col);
            float by = __ldg(bias + col + 1);
            int r1 = row0 + wm * 32 + im * 16 + row_l;
            if (r1 < M) {
                float2 o0 = make_float2(acc[im][in][0] + bx, acc[im][in][1] + by);
                *reinterpret_cast<float2*>(Cout + (size_t)r1 * 384 + col) = o0;
            }
            int r2 = r1 + 8;
            if (r2 < M) {
                float2 o1 = make_float2(acc[im][in][2] + bx, acc[im][in][3] + by);
                *reinterpret_cast<float2*>(Cout + (size_t)r2 * 384 + col) = o1;
            }
        }
    }
}

// ======================= scatter + GRU =====================================
__global__ void scatter_add_kernel(const float* __restrict__ src_rows,
                                   float* __restrict__ agg, int E)
{
    int t = blockIdx.x * blockDim.x + threadIdx.x;
    int edge = t >> 5, lane = t & 31;
    if (edge >= E) return;
    int s = g_src[edge], d = g_dst[edge];
    float4 v = *(reinterpret_cast<const float4*>(src_rows + (size_t)s * C_DIM) + lane);
    atomicAdd(reinterpret_cast<float4*>(agg + (size_t)d * C_DIM) + lane, v);
}

__global__ void gru_update_kernel(const float4* __restrict__ gi,
                                  const float4* __restrict__ gh,
                                  float4* __restrict__ h,
                                  float4* __restrict__ out_relu,
                                  int total4)
{
    int idx = blockIdx.x * blockDim.x + threadIdx.x;
    if (idx >= total4) return;
    int n = idx >> 5, j4 = idx & 31;
    size_t base = (size_t)n * 96;
    float4 ir = gi[base + j4], iz = gi[base + 32 + j4], in = gi[base + 64 + j4];
    float4 hr = gh[base + j4], hz = gh[base + 32 + j4], hn = gh[base + 64 + j4];
    float4 hv = h[idx];
    float4 res, rel;
#pragma unroll
    for (int c = 0; c < 4; c++) {
        float irv = (&ir.x)[c], izv = (&iz.x)[c], inv = (&in.x)[c];
        float hrv = (&hr.x)[c], hzv = (&hz.x)[c], hnv = (&hn.x)[c];
        float hvv = (&hv.x)[c];
        float r = 1.f / (1.f + __expf(-(irv + hrv)));
        float z = 1.f / (1.f + __expf(-(izv + hzv)));
        float nval = tanhf(inv + r * hnv);
        float hnew = (1.f - z) * nval + z * hvv;
        (&res.x)[c] = hnew;
        (&rel.x)[c] = fmaxf(hnew, 0.f);
    }
    h[idx] = res;
    if (out_relu) out_relu[idx] = rel;
}

// ============================ launch =======================================
extern "C" void kernel_launch(void* const* d_in, const int* in_sizes, int n_in,
                              void* d_out, int out_size)
{
    const float* x    = (const float*)d_in[0];
    const int*   e32  = (const int*)  d_in[1];
    const float* w    = (const float*)d_in[2];
    const float* w_ih = (const float*)d_in[3];
    const float* w_hh = (const float*)d_in[4];
    const float* b_ih = (const float*)d_in[5];
    const float* b_hh = (const float*)d_in[6];

    const int N = in_sizes[0] / C_DIM;
    const int E = in_sizes[1] / 2;
    const int L = in_sizes[2] / (C_DIM * C_DIM);

    float *p_h, *p_agg, *p_gi, *p_gh, *p_bl;
    __nv_bfloat16 *p_blh, *p_bll, *p_whh, *p_whl;
    cudaGetSymbolAddress((void**)&p_h,   g_h);
    cudaGetSymbolAddress((void**)&p_agg, g_agg);
    cudaGetSymbolAddress((void**)&p_gi,  g_gi);
    cudaGetSymbolAddress((void**)&p_gh,  g_gh);
    cudaGetSymbolAddress((void**)&p_bl,  g_bl);
    cudaGetSymbolAddress((void**)&p_blh, g_bl_hi);
    cudaGetSymbolAddress((void**)&p_bll, g_bl_lo);
    cudaGetSymbolAddress((void**)&p_whh, g_whh_hi);
    cudaGetSymbolAddress((void**)&p_whl, g_whh_lo);

    cudaFuncSetAttribute(mma_gemm_kernel, cudaFuncAttributeMaxDynamicSharedMemorySize, SM_TOT);

    // edge decode
    int nscan = 1024;
    if (2 * E < nscan) nscan = 2 * E;
    detect_edge_dtype_kernel<<<1, 32>>>(e32, nscan);
    decode_edges_kernel<<<(E + 255) / 256, 256>>>(e32, E);

    // h = x
    const int n4 = N * (C_DIM / 4);
    copy_f4_kernel<<<(n4 + 255) / 256, 256>>>((const float4*)x, (float4*)p_h, n4);

    // B_l = w_ih @ W_l^T  (one batched launch), then split weights to bf16
    gemm_nt_batched_kernel<<<dim3(6, 2, L), 256>>>(w_ih, w, p_bl, 384, C_DIM);
    {
        int nbl = L * 3 * C_DIM * C_DIM;
        split_bf16_kernel<<<(nbl + 255) / 256, 256>>>(p_bl, p_blh, p_bll, nbl);
        int nwh = 3 * C_DIM * C_DIM;
        split_bf16_kernel<<<(nwh + 255) / 256, 256>>>(w_hh, p_whh, p_whl, nwh);
    }

    const int gx = (N + 127) / 128;

    for (int l = 0; l < L; l++) {
        // aggH = 0 ; aggH[dst] += h[src]
        zero_f4_kernel<<<(n4 + 255) / 256, 256>>>((float4*)p_agg, n4);
        {
            long long threads = (long long)E * 32;
            int blocks = (int)((threads + 255) / 256);
            scatter_add_kernel<<<blocks, 256>>>(p_h, p_agg, E);
        }

        // gi = aggH @ B_l^T + b_ih ; gh = h @ w_hh^T + b_hh
        mma_gemm_kernel<<<dim3(gx, 3), 512, SM_TOT>>>(
            p_agg, p_blh + (size_t)l * 3 * C_DIM * C_DIM,
            p_bll + (size_t)l * 3 * C_DIM * C_DIM, b_ih, p_gi, N);
        mma_gemm_kernel<<<dim3(gx, 3), 512, SM_TOT>>>(
            p_h, p_whh, p_whl, b_hh, p_gh, N);

        // h = GRU(gi, gh, h)
        float4* outp = (l == L - 1) ? (float4*)d_out : nullptr;
        gru_update_kernel<<<(n4 + 255) / 256, 256>>>(
            (const float4*)p_gi, (const float4*)p_gh, (float4*)p_h, outp, n4);
    }
}

// round 9
// speedup vs baseline: 1.0058x; 1.0058x over previous
#include <cuda_runtime.h>
#include <cuda_bf16.h>
#include <cstdint>
#include <cstddef>

// ---------------------------------------------------------------------------
// GatedGraphConv (10 layers) + GRUCell.
// Fusion: segment_sum linear => gi = scatter_add(h) @ (w_ih @ W_l^T)^T + b_ih
// GEMMs: mma.sync m16n8k16 bf16 (baseline PTX -- sm_103 target has no
// tcgen05), fp32 accuracy via bf16 hi/lo split: AB ~= AhBh + AhBl + AlBh.
// ---------------------------------------------------------------------------

#define C_DIM 128
#define N_MAX 100352
#define E_MAX 1048576
#define L_MAX 16

__device__ __align__(128) float g_h  [(size_t)N_MAX * C_DIM];
__device__ __align__(128) float g_agg[(size_t)N_MAX * C_DIM];
__device__ __align__(128) float g_gi [(size_t)N_MAX * 3 * C_DIM];
__device__ __align__(128) float g_gh [(size_t)N_MAX * 3 * C_DIM];
__device__ __align__(128) float g_bl [(size_t)L_MAX * 3 * C_DIM * C_DIM];
__device__ __align__(128) __nv_bfloat16 g_bl_hi [(size_t)L_MAX * 3 * C_DIM * C_DIM];
__device__ __align__(128) __nv_bfloat16 g_bl_lo [(size_t)L_MAX * 3 * C_DIM * C_DIM];
__device__ __align__(128) __nv_bfloat16 g_whh_hi[(size_t)3 * C_DIM * C_DIM];
__device__ __align__(128) __nv_bfloat16 g_whh_lo[(size_t)3 * C_DIM * C_DIM];
__device__ __align__(128) int   g_src[E_MAX];
__device__ __align__(128) int   g_dst[E_MAX];
__device__ int g_is64;

// ============================ helpers ======================================
__device__ __forceinline__ uint32_t smem_u32(const void* p) {
    uint32_t a;
    asm("{ .reg .u64 t; cvta.to.shared.u64 t, %1; cvt.u32.u64 %0, t; }" : "=r"(a) : "l"(p));
    return a;
}
__device__ __forceinline__ void ldmatrix_x4(uint32_t& r0, uint32_t& r1,
                                            uint32_t& r2, uint32_t& r3, uint32_t addr) {
    asm volatile("ldmatrix.sync.aligned.m8n8.x4.shared.b16 {%0,%1,%2,%3}, [%4];"
                 : "=r"(r0), "=r"(r1), "=r"(r2), "=r"(r3) : "r"(addr));
}
__device__ __forceinline__ void mma_bf16(float* d, const uint32_t* a, const uint32_t* b) {
    asm volatile(
        "mma.sync.aligned.m16n8k16.row.col.f32.bf16.bf16.f32 "
        "{%0,%1,%2,%3}, {%4,%5,%6,%7}, {%8,%9}, {%0,%1,%2,%3};"
        : "+f"(d[0]), "+f"(d[1]), "+f"(d[2]), "+f"(d[3])
        : "r"(a[0]), "r"(a[1]), "r"(a[2]), "r"(a[3]), "r"(b[0]), "r"(b[1]));
}

// ============================ small kernels ================================
__global__ void detect_edge_dtype_kernel(const int* __restrict__ e32, int nscan) {
    if (threadIdx.x == 0 && blockIdx.x == 0) {
        int acc = 0;
        for (int i = 1; i < nscan; i += 2) acc |= e32[i];
        g_is64 = (acc == 0) ? 1 : 0;
    }
}
__global__ void decode_edges_kernel(const int* __restrict__ e32, int E) {
    int i = blockIdx.x * blockDim.x + threadIdx.x;
    if (i >= E) return;
    if (g_is64) { g_src[i] = e32[2 * (size_t)i]; g_dst[i] = e32[2 * ((size_t)E + i)]; }
    else        { g_src[i] = e32[i];             g_dst[i] = e32[(size_t)E + i]; }
}
__global__ void copy_f4_kernel(const float4* __restrict__ s, float4* __restrict__ d, int n4) {
    int i = blockIdx.x * blockDim.x + threadIdx.x;
    if (i < n4) d[i] = s[i];
}
__global__ void zero_f4_kernel(float4* __restrict__ p, int n4) {
    int i = blockIdx.x * blockDim.x + threadIdx.x;
    if (i < n4) p[i] = make_float4(0.f, 0.f, 0.f, 0.f);
}
__global__ void split_bf16_kernel(const float* __restrict__ src,
                                  __nv_bfloat16* __restrict__ hi,
                                  __nv_bfloat16* __restrict__ lo, int n) {
    int i = blockIdx.x * blockDim.x + threadIdx.x;
    if (i >= n) return;
    float v = src[i];
    __nv_bfloat16 h = __float2bfloat16(v);
    hi[i] = h;
    lo[i] = __float2bfloat16(v - __bfloat162float(h));
}

// ================= SIMT NT GEMM (tiny B_l precompute, batched over z) ======
__global__ void __launch_bounds__(256) gemm_nt_batched_kernel(
    const float* __restrict__ A, const float* __restrict__ Wall,
    float* __restrict__ CoutAll, int M, int nout)
{
    __shared__ float As[64][68];
    __shared__ float Bs[64][68];
    const float* B = Wall + (size_t)blockIdx.z * C_DIM * C_DIM;
    float* Cout = CoutAll + (size_t)blockIdx.z * 3 * C_DIM * C_DIM;
    const int tid = threadIdx.x;
    const int row0 = blockIdx.x * 64, col0 = blockIdx.y * 64;
    const int tx = tid & 15, ty = tid >> 4;
    float acc[4][4];
#pragma unroll
    for (int i = 0; i < 4; i++)
#pragma unroll
        for (int j = 0; j < 4; j++) acc[i][j] = 0.f;
#pragma unroll
    for (int kt = 0; kt < 2; kt++) {
#pragma unroll
        for (int s = 0; s < 4; s++) {
            int i = tid + s * 256, r = i >> 4, c4 = i & 15;
            float4 va = make_float4(0.f, 0.f, 0.f, 0.f);
            if (row0 + r < M)
                va = *reinterpret_cast<const float4*>(A + (size_t)(row0 + r) * C_DIM + kt * 64 + c4 * 4);
            *reinterpret_cast<float4*>(&As[r][c4 * 4]) = va;
            float4 vb = *reinterpret_cast<const float4*>(B + (size_t)(col0 + r) * C_DIM + kt * 64 + c4 * 4);
            *reinterpret_cast<float4*>(&Bs[r][c4 * 4]) = vb;
        }
        __syncthreads();
#pragma unroll
        for (int k4 = 0; k4 < 16; k4++) {
            float4 a[4], b[4];
#pragma unroll
            for (int i = 0; i < 4; i++) a[i] = *reinterpret_cast<const float4*>(&As[ty * 4 + i][k4 * 4]);
#pragma unroll
            for (int j = 0; j < 4; j++) b[j] = *reinterpret_cast<const float4*>(&Bs[tx * 4 + j][k4 * 4]);
#pragma unroll
            for (int i = 0; i < 4; i++)
#pragma unroll
                for (int j = 0; j < 4; j++) {
                    acc[i][j] += a[i].x * b[j].x; acc[i][j] += a[i].y * b[j].y;
                    acc[i][j] += a[i].z * b[j].z; acc[i][j] += a[i].w * b[j].w;
                }
        }
        __syncthreads();
    }
#pragma unroll
    for (int i = 0; i < 4; i++) {
        int r = row0 + ty * 4 + i;
        if (r < M)
#pragma unroll
            for (int j = 0; j < 4; j++)
                Cout[(size_t)r * nout + col0 + tx * 4 + j] = acc[i][j];
    }
}

// ======================= HMMA GEMM (the hot path) ==========================
// C[M x 384] = A[M x 128](fp32) * B[384 x 128]^T(bf16 hi/lo) + bias
// CTA tile 128x128, K=128 fully resident in smem. 512 threads, warp grid
// 4x4, warp tile 32x32 (2 m-frags x 4 n-frags), 3 mma per frag (split).
// Padded smem rows: 136 bf16 = 272 B = 17 x 16B  -> ldmatrix conflict-free.
#define LDA_B 272                 // bytes per padded row
#define TILE_B (128 * LDA_B)      // 34816 bytes per tile
#define SM_TOT (4 * TILE_B)       // A_hi, A_lo, B_hi, B_lo

__global__ void __launch_bounds__(512, 1)
mma_gemm_kernel(const float* __restrict__ A,
                const __nv_bfloat16* __restrict__ Bhi,
                const __nv_bfloat16* __restrict__ Blo,
                const float* __restrict__ bias,
                float* __restrict__ Cout, int M)
{
    extern __shared__ char smem[];
    char* sAhi = smem;
    char* sAlo = smem + TILE_B;
    char* sBhi = smem + 2 * TILE_B;
    char* sBlo = smem + 3 * TILE_B;

    const int tid  = threadIdx.x;
    const int wid  = tid >> 5;
    const int lane = tid & 31;
    const int row0 = blockIdx.x * 128;
    const int col0 = blockIdx.y * 128;

    // ---- load A (fp32), split to bf16 hi/lo, store to padded smem ----
#pragma unroll
    for (int it = 0; it < 8; it++) {
        int idx = tid + it * 512;          // 0..4095 float4 index
        int row = idx >> 5;                // 0..127
        int kk  = (idx & 31) * 4;          // 0..124
        float4 v = make_float4(0.f, 0.f, 0.f, 0.f);
        if (row0 + row < M)
            v = *reinterpret_cast<const float4*>(A + (size_t)(row0 + row) * C_DIM + kk);
        __nv_bfloat16 hx = __float2bfloat16(v.x), hy = __float2bfloat16(v.y);
        __nv_bfloat16 hz = __float2bfloat16(v.z), hw = __float2bfloat16(v.w);
        __nv_bfloat16 ox = __float2bfloat16(v.x - __bfloat162float(hx));
        __nv_bfloat16 oy = __float2bfloat16(v.y - __bfloat162float(hy));
        __nv_bfloat16 oz = __float2bfloat16(v.z - __bfloat162float(hz));
        __nv_bfloat16 ow = __float2bfloat16(v.w - __bfloat162float(hw));
        uint32_t h01 = (uint32_t)__bfloat16_as_ushort(hx) | ((uint32_t)__bfloat16_as_ushort(hy) << 16);
        uint32_t h23 = (uint32_t)__bfloat16_as_ushort(hz) | ((uint32_t)__bfloat16_as_ushort(hw) << 16);
        uint32_t l01 = (uint32_t)__bfloat16_as_ushort(ox) | ((uint32_t)__bfloat16_as_ushort(oy) << 16);
        uint32_t l23 = (uint32_t)__bfloat16_as_ushort(oz) | ((uint32_t)__bfloat16_as_ushort(ow) << 16);
        uint32_t off = (uint32_t)row * LDA_B + kk * 2;
        *reinterpret_cast<uint2*>(sAhi + off) = make_uint2(h01, h23);
        *reinterpret_cast<uint2*>(sAlo + off) = make_uint2(l01, l23);
    }

    // ---- load B (pre-split bf16) to padded smem ----
#pragma unroll
    for (int it = 0; it < 4; it++) {
        int idx = tid + it * 512;          // 0..2047 uint4 index
        int r   = idx >> 4;                // 0..127
        int k0  = (idx & 15) * 8;          // 0..120
        uint4 vh = *reinterpret_cast<const uint4*>(Bhi + (size_t)(col0 + r) * C_DIM + k0);
        uint4 vl = *reinterpret_cast<const uint4*>(Blo + (size_t)(col0 + r) * C_DIM + k0);
        uint32_t off = (uint32_t)r * LDA_B + k0 * 2;
        *reinterpret_cast<uint4*>(sBhi + off) = vh;
        *reinterpret_cast<uint4*>(sBlo + off) = vl;
    }
    __syncthreads();

    // ---- compute: warp (wm, wn) covers rows wm*32..+31, cols wn*32..+31 ----
    const int wm = wid & 3;
    const int wn = wid >> 2;

    // ldmatrix lane addressing
    // A: row = tile_row + lane%16, col byte = (lane/16)*16
    const uint32_t a_base_off =
        (uint32_t)(wm * 32 + (lane & 15)) * LDA_B + (uint32_t)(lane >> 4) * 16;
    uint32_t aHaddr = smem_u32(sAhi) + a_base_off;
    uint32_t aLaddr = smem_u32(sAlo) + a_base_off;
    // B: g = lane/8; row = tile_col + (g>>1)*8 + lane%8 ; col byte = (g&1)*16
    const uint32_t b_base_off =
        (uint32_t)(wn * 32 + ((lane >> 4) & 1) * 8 + (lane & 7)) * LDA_B +
        (uint32_t)((lane >> 3) & 1) * 16;
    uint32_t bHaddr = smem_u32(sBhi) + b_base_off;
    uint32_t bLaddr = smem_u32(sBlo) + b_base_off;

    float acc[2][4][4];
#pragma unroll
    for (int im = 0; im < 2; im++)
#pragma unroll
        for (int in = 0; in < 4; in++)
#pragma unroll
            for (int q = 0; q < 4; q++) acc[im][in][q] = 0.f;

#pragma unroll
    for (int ks = 0; ks < 8; ks++) {
        const uint32_t koff = ks * 32;   // 16 bf16 = 32 bytes per kstep
        uint32_t aH[2][4], aL[2][4], bH[4][2], bL[4][2];
#pragma unroll
        for (int im = 0; im < 2; im++) {
            ldmatrix_x4(aH[im][0], aH[im][1], aH[im][2], aH[im][3],
                        aHaddr + (uint32_t)im * 16 * LDA_B + koff);
            ldmatrix_x4(aL[im][0], aL[im][1], aL[im][2], aL[im][3],
                        aLaddr + (uint32_t)im * 16 * LDA_B + koff);
        }
#pragma unroll
        for (int io = 0; io < 2; io++) {
            uint32_t r0, r1, r2, r3;
            ldmatrix_x4(r0, r1, r2, r3, bHaddr + (uint32_t)io * 16 * LDA_B + koff);
            bH[io * 2 + 0][0] = r0; bH[io * 2 + 0][1] = r1;
            bH[io * 2 + 1][0] = r2; bH[io * 2 + 1][1] = r3;
            ldmatrix_x4(r0, r1, r2, r3, bLaddr + (uint32_t)io * 16 * LDA_B + koff);
            bL[io * 2 + 0][0] = r0; bL[io * 2 + 0][1] = r1;
            bL[io * 2 + 1][0] = r2; bL[io * 2 + 1][1] = r3;
        }
#pragma unroll
        for (int im = 0; im < 2; im++)
#pragma unroll
            for (int in = 0; in < 4; in++) {
                mma_bf16(acc[im][in], aH[im], bH[in]);
                mma_bf16(acc[im][in], aH[im], bL[in]);
                mma_bf16(acc[im][in], aL[im], bH[in]);
            }
    }

    // ---- epilogue ----
    const int row_l = lane >> 2;          // 0..7
    const int col_l = (lane & 3) * 2;     // 0,2,4,6
#pragma unroll
    for (int im = 0; im < 2; im++) {
#pragma unroll
        for (int in = 0; in < 4; in++) {
            int col = col0 + wn * 32 + in * 8 + col_l;
            float bx = __ldg(bias + col);
            float by = __ldg(bias + col + 1);
            int r1 = row0 + wm * 32 + im * 16 + row_l;
            if (r1 < M) {
                float2 o0 = make_float2(acc[im][in][0] + bx, acc[im][in][1] + by);
                *reinterpret_cast<float2*>(Cout + (size_t)r1 * 384 + col) = o0;
            }
            int r2 = r1 + 8;
            if (r2 < M) {
                float2 o1 = make_float2(acc[im][in][2] + bx, acc[im][in][3] + by);
                *reinterpret_cast<float2*>(Cout + (size_t)r2 * 384 + col) = o1;
            }
        }
    }
}

// ======================= scatter + GRU =====================================
__global__ void scatter_add_kernel(const float* __restrict__ src_rows,
                                   float* __restrict__ agg, int E)
{
    int t = blockIdx.x * blockDim.x + threadIdx.x;
    int edge = t >> 5, lane = t & 31;
    if (edge >= E) return;
    int s = g_src[edge], d = g_dst[edge];
    float4 v = *(reinterpret_cast<const float4*>(src_rows + (size_t)s * C_DIM) + lane);
    atomicAdd(reinterpret_cast<float4*>(agg + (size_t)d * C_DIM) + lane, v);
}

__global__ void gru_update_kernel(const float4* __restrict__ gi,
                                  const float4* __restrict__ gh,
                                  float4* __restrict__ h,
                                  float4* __restrict__ out_relu,
                                  int total4)
{
    int idx = blockIdx.x * blockDim.x + threadIdx.x;
    if (idx >= total4) return;
    int n = idx >> 5, j4 = idx & 31;
    size_t base = (size_t)n * 96;
    float4 ir = gi[base + j4], iz = gi[base + 32 + j4], in = gi[base + 64 + j4];
    float4 hr = gh[base + j4], hz = gh[base + 32 + j4], hn = gh[base + 64 + j4];
    float4 hv = h[idx];
    float4 res, rel;
#pragma unroll
    for (int c = 0; c < 4; c++) {
        float irv = (&ir.x)[c], izv = (&iz.x)[c], inv = (&in.x)[c];
        float hrv = (&hr.x)[c], hzv = (&hz.x)[c], hnv = (&hn.x)[c];
        float hvv = (&hv.x)[c];
        float r = 1.f / (1.f + __expf(-(irv + hrv)));
        float z = 1.f / (1.f + __expf(-(izv + hzv)));
        float nval = tanhf(inv + r * hnv);
        float hnew = (1.f - z) * nval + z * hvv;
        (&res.x)[c] = hnew;
        (&rel.x)[c] = fmaxf(hnew, 0.f);
    }
    h[idx] = res;
    if (out_relu) out_relu[idx] = rel;
}

// ============================ launch =======================================
extern "C" void kernel_launch(void* const* d_in, const int* in_sizes, int n_in,
                              void* d_out, int out_size)
{
    const float* x    = (const float*)d_in[0];
    const int*   e32  = (const int*)  d_in[1];
    const float* w    = (const float*)d_in[2];
    const float* w_ih = (const float*)d_in[3];
    const float* w_hh = (const float*)d_in[4];
    const float* b_ih = (const float*)d_in[5];
    const float* b_hh = (const float*)d_in[6];

    const int N = in_sizes[0] / C_DIM;
    const int E = in_sizes[1] / 2;
    const int L = in_sizes[2] / (C_DIM * C_DIM);

    float *p_h, *p_agg, *p_gi, *p_gh, *p_bl;
    __nv_bfloat16 *p_blh, *p_bll, *p_whh, *p_whl;
    cudaGetSymbolAddress((void**)&p_h,   g_h);
    cudaGetSymbolAddress((void**)&p_agg, g_agg);
    cudaGetSymbolAddress((void**)&p_gi,  g_gi);
    cudaGetSymbolAddress((void**)&p_gh,  g_gh);
    cudaGetSymbolAddress((void**)&p_bl,  g_bl);
    cudaGetSymbolAddress((void**)&p_blh, g_bl_hi);
    cudaGetSymbolAddress((void**)&p_bll, g_bl_lo);
    cudaGetSymbolAddress((void**)&p_whh, g_whh_hi);
    cudaGetSymbolAddress((void**)&p_whl, g_whh_lo);

    cudaFuncSetAttribute(mma_gemm_kernel, cudaFuncAttributeMaxDynamicSharedMemorySize, SM_TOT);

    // edge decode
    int nscan = 1024;
    if (2 * E < nscan) nscan = 2 * E;
    detect_edge_dtype_kernel<<<1, 32>>>(e32, nscan);
    decode_edges_kernel<<<(E + 255) / 256, 256>>>(e32, E);

    // h = x
    const int n4 = N * (C_DIM / 4);
    copy_f4_kernel<<<(n4 + 255) / 256, 256>>>((const float4*)x, (float4*)p_h, n4);

    // B_l = w_ih @ W_l^T  (one batched launch), then split weights to bf16
    gemm_nt_batched_kernel<<<dim3(6, 2, L), 256>>>(w_ih, w, p_bl, 384, C_DIM);
    {
        int nbl = L * 3 * C_DIM * C_DIM;
        split_bf16_kernel<<<(nbl + 255) / 256, 256>>>(p_bl, p_blh, p_bll, nbl);
        int nwh = 3 * C_DIM * C_DIM;
        split_bf16_kernel<<<(nwh + 255) / 256, 256>>>(w_hh, p_whh, p_whl, nwh);
    }

    const int gx = (N + 127) / 128;

    for (int l = 0; l < L; l++) {
        // aggH = 0 ; aggH[dst] += h[src]
        zero_f4_kernel<<<(n4 + 255) / 256, 256>>>((float4*)p_agg, n4);
        {
            long long threads = (long long)E * 32;
            int blocks = (int)((threads + 255) / 256);
            scatter_add_kernel<<<blocks, 256>>>(p_h, p_agg, E);
        }

        // gi = aggH @ B_l^T + b_ih ; gh = h @ w_hh^T + b_hh
        mma_gemm_kernel<<<dim3(gx, 3), 512, SM_TOT>>>(
            p_agg, p_blh + (size_t)l * 3 * C_DIM * C_DIM,
            p_bll + (size_t)l * 3 * C_DIM * C_DIM, b_ih, p_gi, N);
        mma_gemm_kernel<<<dim3(gx, 3), 512, SM_TOT>>>(
            p_h, p_whh, p_whl, b_hh, p_gh, N);

        // h = GRU(gi, gh, h)
        float4* outp = (l == L - 1) ? (float4*)d_out : nullptr;
        gru_update_kernel<<<(n4 + 255) / 256, 256>>>(
            (const float4*)p_gi, (const float4*)p_gh, (float4*)p_h, outp, n4);
    }
}

// round 10
// speedup vs baseline: 1.4870x; 1.4784x over previous
#include <cuda_runtime.h>
#include <cuda_bf16.h>
#include <cstdint>
#include <cstddef>

// ---------------------------------------------------------------------------
// GatedGraphConv (10 layers) + GRUCell.
//  - Fusion 1 (algebra): segment_sum is linear => gi = aggH @ (w_ih@W_l^T)^T
//  - Fusion 2 (this round): per layer ONE kernel computes gi & gh via
//    mma.sync bf16 hi/lo-split and applies the GRU in the epilogue.
//    r/z gates: agg@B_l_g^T and h@w_hh_g^T accumulate into the SAME frag.
//  - CSR aggregation (no atomics, no zero pass).
// ---------------------------------------------------------------------------

#define C_DIM 128
#define N_MAX 100352
#define E_MAX 1048576
#define L_MAX 16

__device__ __align__(128) float g_h  [(size_t)N_MAX * C_DIM];
__device__ __align__(128) float g_agg[(size_t)N_MAX * C_DIM];
__device__ __align__(128) float g_bl [(size_t)L_MAX * 3 * C_DIM * C_DIM];
__device__ __align__(128) __nv_bfloat16 g_bl_hi [(size_t)L_MAX * 3 * C_DIM * C_DIM];
__device__ __align__(128) __nv_bfloat16 g_bl_lo [(size_t)L_MAX * 3 * C_DIM * C_DIM];
__device__ __align__(128) __nv_bfloat16 g_whh_hi[(size_t)3 * C_DIM * C_DIM];
__device__ __align__(128) __nv_bfloat16 g_whh_lo[(size_t)3 * C_DIM * C_DIM];
__device__ __align__(128) int g_src[E_MAX];
__device__ __align__(128) int g_dst[E_MAX];
__device__ __align__(128) int g_sorted_src[E_MAX];
__device__ __align__(128) int g_deg    [N_MAX];
__device__ __align__(128) int g_partial[N_MAX];
__device__ __align__(128) int g_rowptr [N_MAX + 1];
__device__ __align__(128) int g_cursor [N_MAX];
__device__ __align__(128) int g_bsums  [256];
__device__ int g_is64;

// ============================ helpers ======================================
__device__ __forceinline__ uint32_t smem_u32(const void* p) {
    uint32_t a;
    asm("{ .reg .u64 t; cvta.to.shared.u64 t, %1; cvt.u32.u64 %0, t; }" : "=r"(a) : "l"(p));
    return a;
}
__device__ __forceinline__ void ldmatrix_x4(uint32_t& r0, uint32_t& r1,
                                            uint32_t& r2, uint32_t& r3, uint32_t addr) {
    asm volatile("ldmatrix.sync.aligned.m8n8.x4.shared.b16 {%0,%1,%2,%3}, [%4];"
                 : "=r"(r0), "=r"(r1), "=r"(r2), "=r"(r3) : "r"(addr));
}
__device__ __forceinline__ void mma_bf16(float* d, const uint32_t* a, const uint32_t* b) {
    asm volatile(
        "mma.sync.aligned.m16n8k16.row.col.f32.bf16.bf16.f32 "
        "{%0,%1,%2,%3}, {%4,%5,%6,%7}, {%8,%9}, {%0,%1,%2,%3};"
        : "+f"(d[0]), "+f"(d[1]), "+f"(d[2]), "+f"(d[3])
        : "r"(a[0]), "r"(a[1]), "r"(a[2]), "r"(a[3]), "r"(b[0]), "r"(b[1]));
}

// ============================ prologue kernels =============================
__global__ void detect_edge_dtype_kernel(const int* __restrict__ e32, int nscan) {
    if (threadIdx.x == 0 && blockIdx.x == 0) {
        int acc = 0;
        for (int i = 1; i < nscan; i += 2) acc |= e32[i];
        g_is64 = (acc == 0) ? 1 : 0;
    }
}
__global__ void decode_edges_kernel(const int* __restrict__ e32, int E) {
    int i = blockIdx.x * blockDim.x + threadIdx.x;
    if (i >= E) return;
    if (g_is64) { g_src[i] = e32[2 * (size_t)i]; g_dst[i] = e32[2 * ((size_t)E + i)]; }
    else        { g_src[i] = e32[i];             g_dst[i] = e32[(size_t)E + i]; }
}
__global__ void copy_f4_kernel(const float4* __restrict__ s, float4* __restrict__ d, int n4) {
    int i = blockIdx.x * blockDim.x + threadIdx.x;
    if (i < n4) d[i] = s[i];
}
__global__ void split_bf16_kernel(const float* __restrict__ src,
                                  __nv_bfloat16* __restrict__ hi,
                                  __nv_bfloat16* __restrict__ lo, int n) {
    int i = blockIdx.x * blockDim.x + threadIdx.x;
    if (i >= n) return;
    float v = src[i];
    __nv_bfloat16 h = __float2bfloat16(v);
    hi[i] = h;
    lo[i] = __float2bfloat16(v - __bfloat162float(h));
}

// ---- CSR build (once per call) ----
__global__ void zero_int_kernel(int* __restrict__ p, int n) {
    int i = blockIdx.x * blockDim.x + threadIdx.x;
    if (i < n) p[i] = 0;
}
__global__ void hist_kernel(int E) {
    int i = blockIdx.x * blockDim.x + threadIdx.x;
    if (i < E) atomicAdd(&g_deg[g_dst[i]], 1);
}
#define SCAN_BLK 1024
__global__ void scan_block_kernel(int N) {
    __shared__ int sh[SCAN_BLK];
    int tid = threadIdx.x;
    int gid = blockIdx.x * SCAN_BLK + tid;
    int v = (gid < N) ? g_deg[gid] : 0;
    sh[tid] = v; __syncthreads();
    for (int off = 1; off < SCAN_BLK; off <<= 1) {
        int t = (tid >= off) ? sh[tid - off] : 0;
        __syncthreads();
        sh[tid] += t;
        __syncthreads();
    }
    if (gid < N) g_partial[gid] = sh[tid] - v;   // exclusive within block
    if (tid == SCAN_BLK - 1) g_bsums[blockIdx.x] = sh[tid];
}
__global__ void scan_sums_kernel(int nb) {
    if (threadIdx.x == 0 && blockIdx.x == 0) {
        int run = 0;
        for (int i = 0; i < nb; i++) { int t = g_bsums[i]; g_bsums[i] = run; run += t; }
    }
}
__global__ void scan_add_kernel(int N, int E) {
    int gid = blockIdx.x * blockDim.x + threadIdx.x;
    if (gid < N) {
        int v = g_partial[gid] + g_bsums[gid / SCAN_BLK];
        g_rowptr[gid] = v;
        g_cursor[gid] = v;
    }
    if (gid == N) g_rowptr[N] = E;
}
__global__ void csr_fill_kernel(int E) {
    int i = blockIdx.x * blockDim.x + threadIdx.x;
    if (i >= E) return;
    int pos = atomicAdd(&g_cursor[g_dst[i]], 1);
    g_sorted_src[pos] = g_src[i];
}

// ---- per-layer aggregation: warp per dst node, register gather-sum ----
__global__ void aggregate_csr_kernel(const float* __restrict__ h,
                                     float* __restrict__ agg, int N)
{
    int t = blockIdx.x * blockDim.x + threadIdx.x;
    int node = t >> 5, lane = t & 31;
    if (node >= N) return;
    int e0 = g_rowptr[node], e1 = g_rowptr[node + 1];
    float4 acc = make_float4(0.f, 0.f, 0.f, 0.f);
    for (int e = e0; e < e1; e++) {
        int s = g_sorted_src[e];
        float4 v = *(reinterpret_cast<const float4*>(h + (size_t)s * C_DIM) + lane);
        acc.x += v.x; acc.y += v.y; acc.z += v.z; acc.w += v.w;
    }
    *(reinterpret_cast<float4*>(agg + (size_t)node * C_DIM) + lane) = acc;
}

// ================= SIMT NT GEMM (tiny B_l precompute, batched over z) ======
__global__ void __launch_bounds__(256) gemm_nt_batched_kernel(
    const float* __restrict__ A, const float* __restrict__ Wall,
    float* __restrict__ CoutAll, int M, int nout)
{
    __shared__ float As[64][68];
    __shared__ float Bs[64][68];
    const float* B = Wall + (size_t)blockIdx.z * C_DIM * C_DIM;
    float* Cout = CoutAll + (size_t)blockIdx.z * 3 * C_DIM * C_DIM;
    const int tid = threadIdx.x;
    const int row0 = blockIdx.x * 64, col0 = blockIdx.y * 64;
    const int tx = tid & 15, ty = tid >> 4;
    float acc[4][4];
#pragma unroll
    for (int i = 0; i < 4; i++)
#pragma unroll
        for (int j = 0; j < 4; j++) acc[i][j] = 0.f;
#pragma unroll
    for (int kt = 0; kt < 2; kt++) {
#pragma unroll
        for (int s = 0; s < 4; s++) {
            int i = tid + s * 256, r = i >> 4, c4 = i & 15;
            float4 va = make_float4(0.f, 0.f, 0.f, 0.f);
            if (row0 + r < M)
                va = *reinterpret_cast<const float4*>(A + (size_t)(row0 + r) * C_DIM + kt * 64 + c4 * 4);
            *reinterpret_cast<float4*>(&As[r][c4 * 4]) = va;
            float4 vb = *reinterpret_cast<const float4*>(B + (size_t)(col0 + r) * C_DIM + kt * 64 + c4 * 4);
            *reinterpret_cast<float4*>(&Bs[r][c4 * 4]) = vb;
        }
        __syncthreads();
#pragma unroll
        for (int k4 = 0; k4 < 16; k4++) {
            float4 a[4], b[4];
#pragma unroll
            for (int i = 0; i < 4; i++) a[i] = *reinterpret_cast<const float4*>(&As[ty * 4 + i][k4 * 4]);
#pragma unroll
            for (int j = 0; j < 4; j++) b[j] = *reinterpret_cast<const float4*>(&Bs[tx * 4 + j][k4 * 4]);
#pragma unroll
            for (int i = 0; i < 4; i++)
#pragma unroll
                for (int j = 0; j < 4; j++) {
                    acc[i][j] += a[i].x * b[j].x; acc[i][j] += a[i].y * b[j].y;
                    acc[i][j] += a[i].z * b[j].z; acc[i][j] += a[i].w * b[j].w;
                }
        }
        __syncthreads();
    }
#pragma unroll
    for (int i = 0; i < 4; i++) {
        int r = row0 + ty * 4 + i;
        if (r < M)
#pragma unroll
            for (int j = 0; j < 4; j++)
                Cout[(size_t)r * nout + col0 + tx * 4 + j] = acc[i][j];
    }
}

// ================== fused layer kernel (GEMMs + GRU) =======================
// CTA: 64 rows x all 384 gate outputs. 512 threads = 16 warps (wm 2 x wn 8);
// warp tile 32 rows x 16 cols per gate. acc sets: r, z (dual-accumulated
// from agg@B_l_g + h@w_hh_g), i_n, h_n. Six B phases reuse one B buffer.
#define F_LDA 272
#define F_ATILE (64 * F_LDA)          // 17408
#define F_BTILE (128 * F_LDA)         // 34816
#define F_SM_AGG_HI 0
#define F_SM_AGG_LO (F_ATILE)
#define F_SM_H_HI   (2 * F_ATILE)
#define F_SM_H_LO   (3 * F_ATILE)
#define F_SM_B_HI   (4 * F_ATILE)               // 69632
#define F_SM_B_LO   (4 * F_ATILE + F_BTILE)     // 104448
#define F_SM_TOT    (4 * F_ATILE + 2 * F_BTILE) // 139264

__device__ __forceinline__ void load_b_tile(char* smem,
    const __nv_bfloat16* __restrict__ bhi, const __nv_bfloat16* __restrict__ blo, int tid)
{
#pragma unroll
    for (int it = 0; it < 4; it++) {
        int idx = tid + it * 512;        // 0..2047 uint4
        int r = idx >> 4, k0 = (idx & 15) * 8;
        uint4 vh = *reinterpret_cast<const uint4*>(bhi + (size_t)r * C_DIM + k0);
        uint4 vl = *reinterpret_cast<const uint4*>(blo + (size_t)r * C_DIM + k0);
        uint32_t off = (uint32_t)r * F_LDA + k0 * 2;
        *reinterpret_cast<uint4*>(smem + F_SM_B_HI + off) = vh;
        *reinterpret_cast<uint4*>(smem + F_SM_B_LO + off) = vl;
    }
}

__device__ __forceinline__ void phase_mma(uint32_t aH_addr, uint32_t aL_addr,
                                          uint32_t bH_addr, uint32_t bL_addr,
                                          float acc[2][2][4])
{
#pragma unroll
    for (int ks = 0; ks < 8; ks++) {
        const uint32_t koff = ks * 32;
        uint32_t aH[2][4], aL[2][4], bH[4], bL[4];
#pragma unroll
        for (int im = 0; im < 2; im++) {
            ldmatrix_x4(aH[im][0], aH[im][1], aH[im][2], aH[im][3],
                        aH_addr + (uint32_t)im * 16 * F_LDA + koff);
            ldmatrix_x4(aL[im][0], aL[im][1], aL[im][2], aL[im][3],
                        aL_addr + (uint32_t)im * 16 * F_LDA + koff);
        }
        ldmatrix_x4(bH[0], bH[1], bH[2], bH[3], bH_addr + koff);
        ldmatrix_x4(bL[0], bL[1], bL[2], bL[3], bL_addr + koff);
#pragma unroll
        for (int im = 0; im < 2; im++)
#pragma unroll
            for (int in = 0; in < 2; in++) {
                mma_bf16(acc[im][in], aH[im], &bH[in * 2]);
                mma_bf16(acc[im][in], aH[im], &bL[in * 2]);
                mma_bf16(acc[im][in], aL[im], &bH[in * 2]);
            }
    }
}

__device__ __forceinline__ float sigmoidf_(float x) {
    return 1.f / (1.f + __expf(-x));
}

__global__ void __launch_bounds__(512, 1)
fused_layer_kernel(const float* __restrict__ agg, float* __restrict__ h,
                   const __nv_bfloat16* __restrict__ Blh, const __nv_bfloat16* __restrict__ Bll,
                   const __nv_bfloat16* __restrict__ Whh, const __nv_bfloat16* __restrict__ Whl,
                   const float* __restrict__ b_ih, const float* __restrict__ b_hh,
                   float* __restrict__ out_relu, int M)
{
    extern __shared__ char smem[];
    const int tid  = threadIdx.x;
    const int wid  = tid >> 5;
    const int lane = tid & 31;
    const int row0 = blockIdx.x * 64;
    const int wm = wid & 1;       // 2 row groups of 32
    const int wn = wid >> 1;      // 8 col groups of 16

    // ---- load A tiles: agg + h (fp32 -> bf16 hi/lo split) ----
#pragma unroll
    for (int it = 0; it < 4; it++) {
        int idx = tid + it * 512;        // 0..2047 float4
        int row = idx >> 5;              // 0..63
        int kk  = (idx & 31) * 4;
        bool ok = (row0 + row < M);
        const float4* pa = reinterpret_cast<const float4*>(agg + (size_t)(row0 + row) * C_DIM + kk);
        const float4* ph = reinterpret_cast<const float4*>(h   + (size_t)(row0 + row) * C_DIM + kk);
        float4 va = ok ? *pa : make_float4(0.f, 0.f, 0.f, 0.f);
        float4 vh = ok ? *ph : make_float4(0.f, 0.f, 0.f, 0.f);
        uint32_t off = (uint32_t)row * F_LDA + kk * 2;
#pragma unroll
        for (int m = 0; m < 2; m++) {
            float4 v = m ? vh : va;
            __nv_bfloat16 hx = __float2bfloat16(v.x), hy = __float2bfloat16(v.y);
            __nv_bfloat16 hz = __float2bfloat16(v.z), hw = __float2bfloat16(v.w);
            __nv_bfloat16 ox = __float2bfloat16(v.x - __bfloat162float(hx));
            __nv_bfloat16 oy = __float2bfloat16(v.y - __bfloat162float(hy));
            __nv_bfloat16 oz = __float2bfloat16(v.z - __bfloat162float(hz));
            __nv_bfloat16 ow = __float2bfloat16(v.w - __bfloat162float(hw));
            uint32_t h01 = (uint32_t)__bfloat16_as_ushort(hx) | ((uint32_t)__bfloat16_as_ushort(hy) << 16);
            uint32_t h23 = (uint32_t)__bfloat16_as_ushort(hz) | ((uint32_t)__bfloat16_as_ushort(hw) << 16);
            uint32_t l01 = (uint32_t)__bfloat16_as_ushort(ox) | ((uint32_t)__bfloat16_as_ushort(oy) << 16);
            uint32_t l23 = (uint32_t)__bfloat16_as_ushort(oz) | ((uint32_t)__bfloat16_as_ushort(ow) << 16);
            int base_hi = m ? F_SM_H_HI : F_SM_AGG_HI;
            int base_lo = m ? F_SM_H_LO : F_SM_AGG_LO;
            *reinterpret_cast<uint2*>(smem + base_hi + off) = make_uint2(h01, h23);
            *reinterpret_cast<uint2*>(smem + base_lo + off) = make_uint2(l01, l23);
        }
    }

    // ---- fragment addressing ----
    const uint32_t sb = smem_u32(smem);
    const uint32_t a_off =
        (uint32_t)(wm * 32 + (lane & 15)) * F_LDA + (uint32_t)(lane >> 4) * 16;
    const uint32_t aggH = sb + F_SM_AGG_HI + a_off;
    const uint32_t aggL = sb + F_SM_AGG_LO + a_off;
    const uint32_t hH   = sb + F_SM_H_HI + a_off;
    const uint32_t hL   = sb + F_SM_H_LO + a_off;
    const uint32_t b_off =
        (uint32_t)(wn * 16 + ((lane >> 4) & 1) * 8 + (lane & 7)) * F_LDA +
        (uint32_t)((lane >> 3) & 1) * 16;
    const uint32_t bH = sb + F_SM_B_HI + b_off;
    const uint32_t bL = sb + F_SM_B_LO + b_off;

    float acc_r [2][2][4], acc_z [2][2][4], acc_in[2][2][4], acc_hn[2][2][4];
#pragma unroll
    for (int im = 0; im < 2; im++)
#pragma unroll
        for (int in = 0; in < 2; in++)
#pragma unroll
            for (int q = 0; q < 4; q++) {
                acc_r[im][in][q] = 0.f; acc_z[im][in][q] = 0.f;
                acc_in[im][in][q] = 0.f; acc_hn[im][in][q] = 0.f;
            }

    // ---- 6 phases: (gate r: Bl, Whh) (gate z: Bl, Whh) (gate n: Bl->in, Whh->hn)
    load_b_tile(smem, Blh + 0 * 16384, Bll + 0 * 16384, tid);
    __syncthreads();
    phase_mma(aggH, aggL, bH, bL, acc_r);
    __syncthreads();
    load_b_tile(smem, Whh + 0 * 16384, Whl + 0 * 16384, tid);
    __syncthreads();
    phase_mma(hH, hL, bH, bL, acc_r);
    __syncthreads();
    load_b_tile(smem, Blh + 1 * 16384, Bll + 1 * 16384, tid);
    __syncthreads();
    phase_mma(aggH, aggL, bH, bL, acc_z);
    __syncthreads();
    load_b_tile(smem, Whh + 1 * 16384, Whl + 1 * 16384, tid);
    __syncthreads();
    phase_mma(hH, hL, bH, bL, acc_z);
    __syncthreads();
    load_b_tile(smem, Blh + 2 * 16384, Bll + 2 * 16384, tid);
    __syncthreads();
    phase_mma(aggH, aggL, bH, bL, acc_in);
    __syncthreads();
    load_b_tile(smem, Whh + 2 * 16384, Whl + 2 * 16384, tid);
    __syncthreads();
    phase_mma(hH, hL, bH, bL, acc_hn);

    // ---- epilogue: GRU + in-place h update (CTA owns its 64 rows) ----
    const int row_l = lane >> 2;
    const int col_l = (lane & 3) * 2;
#pragma unroll
    for (int in = 0; in < 2; in++) {
        const int c = wn * 16 + in * 8 + col_l;     // col within gate block
        const float bir0 = __ldg(b_ih + c),       bir1 = __ldg(b_ih + c + 1);
        const float bhr0 = __ldg(b_hh + c),       bhr1 = __ldg(b_hh + c + 1);
        const float biz0 = __ldg(b_ih + 128 + c), biz1 = __ldg(b_ih + 129 + c);
        const float bhz0 = __ldg(b_hh + 128 + c), bhz1 = __ldg(b_hh + 129 + c);
        const float bin0 = __ldg(b_ih + 256 + c), bin1 = __ldg(b_ih + 257 + c);
        const float bhn0 = __ldg(b_hh + 256 + c), bhn1 = __ldg(b_hh + 257 + c);
#pragma unroll
        for (int im = 0; im < 2; im++) {
#pragma unroll
            for (int q = 0; q < 2; q++) {
                int r = row0 + wm * 32 + im * 16 + q * 8 + row_l;
                if (r >= M) continue;
                float2 hold = *reinterpret_cast<const float2*>(h + (size_t)r * C_DIM + c);
                float rr0 = sigmoidf_(acc_r[im][in][q * 2 + 0] + bir0 + bhr0);
                float rr1 = sigmoidf_(acc_r[im][in][q * 2 + 1] + bir1 + bhr1);
                float zz0 = sigmoidf_(acc_z[im][in][q * 2 + 0] + biz0 + bhz0);
                float zz1 = sigmoidf_(acc_z[im][in][q * 2 + 1] + biz1 + bhz1);
                float nn0 = tanhf(acc_in[im][in][q * 2 + 0] + bin0 + rr0 * (acc_hn[im][in][q * 2 + 0] + bhn0));
                float nn1 = tanhf(acc_in[im][in][q * 2 + 1] + bin1 + rr1 * (acc_hn[im][in][q * 2 + 1] + bhn1));
                float h0 = (1.f - zz0) * nn0 + zz0 * hold.x;
                float h1 = (1.f - zz1) * nn1 + zz1 * hold.y;
                *reinterpret_cast<float2*>(h + (size_t)r * C_DIM + c) = make_float2(h0, h1);
                if (out_relu)
                    *reinterpret_cast<float2*>(out_relu + (size_t)r * C_DIM + c) =
                        make_float2(fmaxf(h0, 0.f), fmaxf(h1, 0.f));
            }
        }
    }
}

// ============================ launch =======================================
extern "C" void kernel_launch(void* const* d_in, const int* in_sizes, int n_in,
                              void* d_out, int out_size)
{
    const float* x    = (const float*)d_in[0];
    const int*   e32  = (const int*)  d_in[1];
    const float* w    = (const float*)d_in[2];
    const float* w_ih = (const float*)d_in[3];
    const float* w_hh = (const float*)d_in[4];
    const float* b_ih = (const float*)d_in[5];
    const float* b_hh = (const float*)d_in[6];

    const int N = in_sizes[0] / C_DIM;
    const int E = in_sizes[1] / 2;
    const int L = in_sizes[2] / (C_DIM * C_DIM);

    float *p_h, *p_agg, *p_bl;
    __nv_bfloat16 *p_blh, *p_bll, *p_whh, *p_whl;
    cudaGetSymbolAddress((void**)&p_h,   g_h);
    cudaGetSymbolAddress((void**)&p_agg, g_agg);
    cudaGetSymbolAddress((void**)&p_bl,  g_bl);
    cudaGetSymbolAddress((void**)&p_blh, g_bl_hi);
    cudaGetSymbolAddress((void**)&p_bll, g_bl_lo);
    cudaGetSymbolAddress((void**)&p_whh, g_whh_hi);
    cudaGetSymbolAddress((void**)&p_whl, g_whh_lo);
    int *p_deg;
    cudaGetSymbolAddress((void**)&p_deg, g_deg);

    cudaFuncSetAttribute(fused_layer_kernel,
                         cudaFuncAttributeMaxDynamicSharedMemorySize, F_SM_TOT);

    // ---- edges + CSR (once) ----
    int nscan = 1024;
    if (2 * E < nscan) nscan = 2 * E;
    detect_edge_dtype_kernel<<<1, 32>>>(e32, nscan);
    decode_edges_kernel<<<(E + 255) / 256, 256>>>(e32, E);
    zero_int_kernel<<<(N + 255) / 256, 256>>>(p_deg, N);
    hist_kernel<<<(E + 255) / 256, 256>>>(E);
    const int nb = (N + SCAN_BLK - 1) / SCAN_BLK;
    scan_block_kernel<<<nb, SCAN_BLK>>>(N);
    scan_sums_kernel<<<1, 32>>>(nb);
    scan_add_kernel<<<(N + 1 + 255) / 256, 256>>>(N, E);
    csr_fill_kernel<<<(E + 255) / 256, 256>>>(E);

    // ---- h = x ----
    const int n4 = N * (C_DIM / 4);
    copy_f4_kernel<<<(n4 + 255) / 256, 256>>>((const float4*)x, (float4*)p_h, n4);

    // ---- B_l = w_ih @ W_l^T, then split weights to bf16 hi/lo ----
    gemm_nt_batched_kernel<<<dim3(6, 2, L), 256>>>(w_ih, w, p_bl, 384, C_DIM);
    {
        int nbl = L * 3 * C_DIM * C_DIM;
        split_bf16_kernel<<<(nbl + 255) / 256, 256>>>(p_bl, p_blh, p_bll, nbl);
        int nwh = 3 * C_DIM * C_DIM;
        split_bf16_kernel<<<(nwh + 255) / 256, 256>>>(w_hh, p_whh, p_whl, nwh);
    }

    const int gx = (N + 63) / 64;
    const int agg_blocks = (N * 32 + 255) / 256;

    for (int l = 0; l < L; l++) {
        aggregate_csr_kernel<<<agg_blocks, 256>>>(p_h, p_agg, N);
        float* outp = (l == L - 1) ? (float*)d_out : nullptr;
        fused_layer_kernel<<<gx, 512, F_SM_TOT>>>(
            p_agg, p_h,
            p_blh + (size_t)l * 3 * C_DIM * C_DIM,
            p_bll + (size_t)l * 3 * C_DIM * C_DIM,
            p_whh, p_whl, b_ih, b_hh, outp, N);
    }
}